// round 10
// baseline (speedup 1.0000x reference)
#include <cuda_runtime.h>
#include <cuda_bf16.h>
#include <cstdint>

#define NU 100000
#define NI 100000
#define D  128
#define ECAP 600000

typedef unsigned long long ull;

// ---------------- scratch (static device globals; no allocation) ----------------
__device__ __align__(16) float g_agg_ui[(size_t)NI * D];
__device__ __align__(16) float g_agg_iu[(size_t)NU * D];
__device__ __align__(16) float g_agg_uu[(size_t)NU * D];
__device__ float g_deg_ui[NI];
__device__ float g_deg_iu[NU];
__device__ float g_deg_uu[NU];

// CSR build scratch
__device__ int g_cnt[3 * NU];
__device__ int g_off[3 * NU];
__device__ int g_cur[3 * NU];
__device__ int g_csr[3 * ECAP];

// ---------------- packed f32x2 helpers (sm_103a) ----------------
__device__ __forceinline__ void fma2(ull& d, ull a, ull b) {
    asm("fma.rn.f32x2 %0, %1, %2, %0;" : "+l"(d) : "l"(a), "l"(b));
}
__device__ __forceinline__ ull splat2(float x) {
    ull r; asm("mov.b64 %0, {%1, %1};" : "=l"(r) : "f"(x)); return r;
}
__device__ __forceinline__ float2 unpack2(ull v) {
    float lo, hi; asm("mov.b64 {%0, %1}, %2;" : "=f"(lo), "=f"(hi) : "l"(v));
    return make_float2(lo, hi);
}

// ---------------- 1) zero CSR counters ----------------
__global__ void zero_cnt_kernel() {
    int i = blockIdx.x * blockDim.x + threadIdx.x;
    if (i < 3 * NU) { g_cnt[i] = 0; g_cur[i] = 0; }
}

// ---------------- 2) histogram of dst per etype ----------------
__global__ void hist_kernel(const int* __restrict__ d0, int E0,
                            const int* __restrict__ d1, int E1,
                            const int* __restrict__ d2, int E2)
{
    int i = blockIdx.x * blockDim.x + threadIdx.x;
    if (i < E0)                { atomicAdd(&g_cnt[d0[i]], 1); }
    else if (i < E0 + E1)      { atomicAdd(&g_cnt[NU + d1[i - E0]], 1); }
    else if (i < E0 + E1 + E2) { atomicAdd(&g_cnt[2 * NU + d2[i - E0 - E1]], 1); }
}

// ---------------- 3) exclusive scan over 3*NU counts (single block) ----------------
__global__ void scan_kernel() {
    const int Ntot = 3 * NU;
    const int t = threadIdx.x;
    const int per = (Ntot + 1023) / 1024;
    const int s0 = t * per;
    const int s1 = (s0 + per < Ntot) ? s0 + per : Ntot;

    int sum = 0;
    for (int i = s0; i < s1; ++i) sum += g_cnt[i];

    const unsigned lane = t & 31, wid = t >> 5;
    int v = sum;
#pragma unroll
    for (int o = 1; o < 32; o <<= 1) {
        int u = __shfl_up_sync(0xffffffffu, v, o);
        if (lane >= o) v += u;
    }
    __shared__ int wsum[32];
    if (lane == 31) wsum[wid] = v;
    __syncthreads();
    if (wid == 0) {
        int w = wsum[lane];
#pragma unroll
        for (int o = 1; o < 32; o <<= 1) {
            int u = __shfl_up_sync(0xffffffffu, w, o);
            if (lane >= o) w += u;
        }
        wsum[lane] = w;
    }
    __syncthreads();
    int excl = v - sum + (wid > 0 ? wsum[wid - 1] : 0);

    int run = excl;
    for (int i = s0; i < s1; ++i) { g_off[i] = run; run += g_cnt[i]; }
}

// ---------------- 4) fill CSR slots ----------------
__global__ void fill_kernel(const int* __restrict__ s0p, const int* __restrict__ d0, int E0,
                            const int* __restrict__ s1p, const int* __restrict__ d1, int E1,
                            const int* __restrict__ s2p, const int* __restrict__ d2, int E2)
{
    int i = blockIdx.x * blockDim.x + threadIdx.x;
    int g, s;
    if (i < E0)                { g = d0[i];                s = s0p[i]; }
    else if (i < E0 + E1)      { g = NU + d1[i - E0];      s = s1p[i - E0]; }
    else if (i < E0 + E1 + E2) { g = 2 * NU + d2[i - E0 - E1]; s = s2p[i - E0 - E1]; }
    else return;
    int pos = g_off[g] + atomicAdd(&g_cur[g], 1);
    g_csr[pos] = s;
}

// ---------------- 5) gather-aggregate: one warp per (etype, node) ----------------
__global__ __launch_bounds__(256) void csr_agg_kernel(
    const float* __restrict__ feat_user, const float* __restrict__ feat_item)
{
    int g    = blockIdx.x * 8 + (threadIdx.x >> 5);
    int lane = threadIdx.x & 31;
    if (g >= 3 * NU) return;

    int et   = g / NU;
    int node = g - et * NU;

    const float* feat = (et == 1) ? feat_item : feat_user;
    float* agg = (et == 0) ? g_agg_ui : (et == 1) ? g_agg_iu : g_agg_uu;
    float* deg = (et == 0) ? g_deg_ui : (et == 1) ? g_deg_iu : g_deg_uu;

    int off = g_off[g];
    int n   = g_cnt[g];

    float4 acc0 = make_float4(0.f, 0.f, 0.f, 0.f);
    float4 acc1 = make_float4(0.f, 0.f, 0.f, 0.f);

    for (int base = 0; base < n; base += 32) {
        int m = (n - base < 32) ? (n - base) : 32;
        int idx = (lane < m) ? g_csr[off + base + lane] : 0;
        int j = 0;
        for (; j + 2 <= m; j += 2) {
            int sA = __shfl_sync(0xffffffffu, idx, j);
            int sB = __shfl_sync(0xffffffffu, idx, j + 1);
            float4 vA = reinterpret_cast<const float4*>(feat + (size_t)sA * D)[lane];
            float4 vB = reinterpret_cast<const float4*>(feat + (size_t)sB * D)[lane];
            acc0.x += vA.x; acc0.y += vA.y; acc0.z += vA.z; acc0.w += vA.w;
            acc1.x += vB.x; acc1.y += vB.y; acc1.z += vB.z; acc1.w += vB.w;
        }
        if (j < m) {
            int sA = __shfl_sync(0xffffffffu, idx, j);
            float4 vA = reinterpret_cast<const float4*>(feat + (size_t)sA * D)[lane];
            acc0.x += vA.x; acc0.y += vA.y; acc0.z += vA.z; acc0.w += vA.w;
        }
    }
    acc0.x += acc1.x; acc0.y += acc1.y; acc0.z += acc1.z; acc0.w += acc1.w;

    reinterpret_cast<float4*>(agg + (size_t)node * D)[lane] = acc0;
    if (lane == 0) deg[node] = (float)n;
}

// ---------------- 6) merged fused GEMM (item + user in ONE grid) ----------------
// blocks [0, GB_I)       : item  : out_item = mask_ui .* ((agg_ui/deg_ui)@W_ui + b_ui)
// blocks [GB_I, GB_I+GB_U): user : out_user = mask_iu .* ((agg_iu/deg_iu)@W_iu + b_iu)
//                                           + mask_uu .* ((agg_uu/deg_uu)@W_uu + b_uu)
#define ASTRIDE 68   // mult of 4 -> 16B-aligned row-pair LDS.128 loads
#define GB_I ((NI + 63) / 64)
#define GB_U ((NU + 63) / 64)

__global__ __launch_bounds__(256) void gemm_fused_kernel(
    const float* __restrict__ W_ui, const float* __restrict__ b_ui,
    const float* __restrict__ W_iu, const float* __restrict__ b_iu,
    const float* __restrict__ W_uu, const float* __restrict__ b_uu,
    float* __restrict__ out_item, float* __restrict__ out_user)
{
    __shared__ __align__(16) ull   W_s2[16 * D];        // 16 KB: W chunk, values splatted {w,w}
    __shared__ __align__(16) float A_s[16 * ASTRIDE];   // 4.3 KB: A chunk, k-major, pre-scaled
    __shared__ float s2_s[2][64];
    __shared__ float b2_s[2][D];

    const int t  = threadIdx.x;
    const int tx = t & 31;
    const int ty = t >> 5;

    const int mode = (blockIdx.x < GB_I) ? 0 : 1;
    const int blk  = (mode == 0) ? blockIdx.x : blockIdx.x - GB_I;
    const int m0   = blk * 64;
    const int M    = (mode == 0) ? NI : NU;
    float* out     = (mode == 0) ? out_item : out_user;
    const float* W0 = (mode == 0) ? W_ui : W_iu;
    const float* B0 = (mode == 0) ? b_ui : b_iu;
    const float* W1 = W_uu;
    const float* B1 = b_uu;

    const int net = (mode == 0) ? 1 : 2;
    const float* Asel[2];
    const float* dsel[2];
    if (mode == 0) { Asel[0] = g_agg_ui; dsel[0] = g_deg_ui; Asel[1] = g_agg_ui; dsel[1] = g_deg_ui; }
    else           { Asel[0] = g_agg_iu; dsel[0] = g_deg_iu; Asel[1] = g_agg_uu; dsel[1] = g_deg_uu; }

    if (t < 128) {
        int e = t >> 6, r = t & 63;
        if (e < net) {
            int row = m0 + r;
            float dg = (row < M) ? dsel[e][row] : 0.f;
            s2_s[e][r] = (dg > 0.f) ? (1.f / dg) : 0.f;
        } else {
            s2_s[e][r] = 0.f;
        }
    }
    if (t < D) b2_s[0][t] = B0[t];
    else if (t < 2 * D) b2_s[1][t - D] = (net == 2) ? B1[t - D] : 0.f;

    ull acc2[4][4];
#pragma unroll
    for (int p = 0; p < 4; ++p)
#pragma unroll
        for (int c = 0; c < 4; ++c) acc2[p][c] = 0ull;

    const int ar = t >> 2;
    const int ac = (t & 3) * 4;
    const int arow = m0 + ar;

    for (int e = 0; e < net; ++e) {
        const float* A = Asel[e];
        const float* W = (e == 0) ? W0 : W1;
#pragma unroll 1
        for (int kc = 0; kc < 8; ++kc) {
            __syncthreads();
            // stage W chunk pre-splatted: 512 float4 loads -> 2048 ull stores (8/thread)
            {
                const float4* Wg = reinterpret_cast<const float4*>(W + (size_t)kc * 16 * D);
#pragma unroll
                for (int h = 0; h < 2; ++h) {
                    int f = t + h * 256;           // float4 index: k = f>>5, col4 = f&31
                    float4 v = Wg[f];
                    ull* dst = &W_s2[(f >> 5) * D + (f & 31) * 4];
                    dst[0] = splat2(v.x);
                    dst[1] = splat2(v.y);
                    dst[2] = splat2(v.z);
                    dst[3] = splat2(v.w);
                }
            }
            // stage A chunk (transposed to k-major) with 1/deg folded in
            {
                float4 v = make_float4(0.f, 0.f, 0.f, 0.f);
                if (arow < M)
                    v = *reinterpret_cast<const float4*>(A + (size_t)arow * D + kc * 16 + ac);
                float sc = s2_s[e][ar];
                A_s[(ac + 0) * ASTRIDE + ar] = v.x * sc;
                A_s[(ac + 1) * ASTRIDE + ar] = v.y * sc;
                A_s[(ac + 2) * ASTRIDE + ar] = v.z * sc;
                A_s[(ac + 3) * ASTRIDE + ar] = v.w * sc;
            }
            __syncthreads();

#pragma unroll
            for (int k = 0; k < 16; ++k) {
                const float* As = &A_s[k * ASTRIDE + ty * 8];
                ulonglong2 p0 = *reinterpret_cast<const ulonglong2*>(As);
                ulonglong2 p1 = *reinterpret_cast<const ulonglong2*>(As + 4);
                ull a0 = p0.x, a1 = p0.y, a2 = p1.x, a3 = p1.y;
                const ull* Ws = &W_s2[k * D + tx * 4];
                ulonglong2 q0 = *reinterpret_cast<const ulonglong2*>(Ws);
                ulonglong2 q1 = *reinterpret_cast<const ulonglong2*>(Ws + 2);
                ull w0 = q0.x, w1 = q0.y, w2 = q1.x, w3 = q1.y;
                fma2(acc2[0][0], a0, w0); fma2(acc2[0][1], a0, w1);
                fma2(acc2[0][2], a0, w2); fma2(acc2[0][3], a0, w3);
                fma2(acc2[1][0], a1, w0); fma2(acc2[1][1], a1, w1);
                fma2(acc2[1][2], a1, w2); fma2(acc2[1][3], a1, w3);
                fma2(acc2[2][0], a2, w0); fma2(acc2[2][1], a2, w1);
                fma2(acc2[2][2], a2, w2); fma2(acc2[2][3], a2, w3);
                fma2(acc2[3][0], a3, w0); fma2(acc2[3][1], a3, w1);
                fma2(acc2[3][2], a3, w2); fma2(acc2[3][3], a3, w3);
            }
        }
    }

#pragma unroll
    for (int p = 0; p < 4; ++p) {
        int lr0 = ty * 8 + 2 * p;
        int row0 = m0 + lr0;
        float mask0_lo = (s2_s[0][lr0]     > 0.f) ? 1.f : 0.f;
        float mask0_hi = (s2_s[0][lr0 + 1] > 0.f) ? 1.f : 0.f;
        float mask1_lo = (s2_s[1][lr0]     > 0.f) ? 1.f : 0.f;
        float mask1_hi = (s2_s[1][lr0 + 1] > 0.f) ? 1.f : 0.f;

        float2 v0 = unpack2(acc2[p][0]);
        float2 v1 = unpack2(acc2[p][1]);
        float2 v2 = unpack2(acc2[p][2]);
        float2 v3 = unpack2(acc2[p][3]);

        const float* bb0 = &b2_s[0][tx * 4];
        const float* bb1 = &b2_s[1][tx * 4];

        if (row0 < M) {
            float4 o;
            o.x = v0.x + mask0_lo * bb0[0] + mask1_lo * bb1[0];
            o.y = v1.x + mask0_lo * bb0[1] + mask1_lo * bb1[1];
            o.z = v2.x + mask0_lo * bb0[2] + mask1_lo * bb1[2];
            o.w = v3.x + mask0_lo * bb0[3] + mask1_lo * bb1[3];
            reinterpret_cast<float4*>(out + (size_t)row0 * D)[tx] = o;
        }
        if (row0 + 1 < M) {
            float4 o;
            o.x = v0.y + mask0_hi * bb0[0] + mask1_hi * bb1[0];
            o.y = v1.y + mask0_hi * bb0[1] + mask1_hi * bb1[1];
            o.z = v2.y + mask0_hi * bb0[2] + mask1_hi * bb1[2];
            o.w = v3.y + mask0_hi * bb0[3] + mask1_hi * bb1[3];
            reinterpret_cast<float4*>(out + (size_t)(row0 + 1) * D)[tx] = o;
        }
    }
}

extern "C" void kernel_launch(void* const* d_in, const int* in_sizes, int n_in,
                              void* d_out, int out_size)
{
    const float* feat_user = (const float*)d_in[0];
    const float* feat_item = (const float*)d_in[1];
    const float* W_ui = (const float*)d_in[2];
    const float* b_ui = (const float*)d_in[3];
    const float* W_iu = (const float*)d_in[4];
    const float* b_iu = (const float*)d_in[5];
    const float* W_uu = (const float*)d_in[6];
    const float* b_uu = (const float*)d_in[7];
    const int* src_ui = (const int*)d_in[8];
    const int* dst_ui = (const int*)d_in[9];
    const int* src_iu = (const int*)d_in[10];
    const int* dst_iu = (const int*)d_in[11];
    const int* src_uu = (const int*)d_in[12];
    const int* dst_uu = (const int*)d_in[13];

    const int E_ui = in_sizes[8];
    const int E_iu = in_sizes[10];
    const int E_uu = in_sizes[12];
    const int Etot = E_ui + E_iu + E_uu;

    float* out      = (float*)d_out;
    float* out_user = out;
    float* out_item = out + (size_t)NU * D;

    (void)n_in; (void)out_size;

    // CSR build + gather aggregation (no float atomics, no big zero pass)
    zero_cnt_kernel<<<(3 * NU + 255) / 256, 256>>>();
    hist_kernel<<<(Etot + 255) / 256, 256>>>(dst_ui, E_ui, dst_iu, E_iu, dst_uu, E_uu);
    scan_kernel<<<1, 1024>>>();
    fill_kernel<<<(Etot + 255) / 256, 256>>>(src_ui, dst_ui, E_ui,
                                             src_iu, dst_iu, E_iu,
                                             src_uu, dst_uu, E_uu);
    csr_agg_kernel<<<(3 * NU + 7) / 8, 256>>>(feat_user, feat_item);

    // merged fused projection: item blocks + user blocks in one grid
    gemm_fused_kernel<<<GB_I + GB_U, 256>>>(W_ui, b_ui, W_iu, b_iu, W_uu, b_uu,
                                            out_item, out_user);
}

// round 17
// speedup vs baseline: 1.1547x; 1.1547x over previous
#include <cuda_runtime.h>
#include <cuda_bf16.h>
#include <cstdint>

#define NU 100000
#define NI 100000
#define D  128
#define ECAP 600000

// ---------------- scratch (static device globals; no allocation) ----------------
__device__ __align__(16) float g_agg_ui[(size_t)NI * D];
__device__ __align__(16) float g_agg_iu[(size_t)NU * D];
__device__ __align__(16) float g_agg_uu[(size_t)NU * D];
__device__ float g_deg_ui[NI];
__device__ float g_deg_iu[NU];
__device__ float g_deg_uu[NU];

// CSR build scratch
__device__ int g_cnt[3 * NU];
__device__ int g_off[3 * NU];
__device__ int g_cur[3 * NU];
__device__ int g_csr[3 * ECAP];

// ---------------- 1) zero CSR counters ----------------
__global__ void zero_cnt_kernel() {
    int i = blockIdx.x * blockDim.x + threadIdx.x;
    if (i < 3 * NU) { g_cnt[i] = 0; g_cur[i] = 0; }
}

// ---------------- 2) histogram of dst per etype ----------------
__global__ void hist_kernel(const int* __restrict__ d0, int E0,
                            const int* __restrict__ d1, int E1,
                            const int* __restrict__ d2, int E2)
{
    int i = blockIdx.x * blockDim.x + threadIdx.x;
    if (i < E0)                { atomicAdd(&g_cnt[d0[i]], 1); }
    else if (i < E0 + E1)      { atomicAdd(&g_cnt[NU + d1[i - E0]], 1); }
    else if (i < E0 + E1 + E2) { atomicAdd(&g_cnt[2 * NU + d2[i - E0 - E1]], 1); }
}

// ---------------- 3) exclusive scan over 3*NU counts (single block) ----------------
__global__ void scan_kernel() {
    const int Ntot = 3 * NU;
    const int t = threadIdx.x;
    const int per = (Ntot + 1023) / 1024;
    const int s0 = t * per;
    const int s1 = (s0 + per < Ntot) ? s0 + per : Ntot;

    int sum = 0;
    for (int i = s0; i < s1; ++i) sum += g_cnt[i];

    const unsigned lane = t & 31, wid = t >> 5;
    int v = sum;
#pragma unroll
    for (int o = 1; o < 32; o <<= 1) {
        int u = __shfl_up_sync(0xffffffffu, v, o);
        if (lane >= o) v += u;
    }
    __shared__ int wsum[32];
    if (lane == 31) wsum[wid] = v;
    __syncthreads();
    if (wid == 0) {
        int w = wsum[lane];
#pragma unroll
        for (int o = 1; o < 32; o <<= 1) {
            int u = __shfl_up_sync(0xffffffffu, w, o);
            if (lane >= o) w += u;
        }
        wsum[lane] = w;
    }
    __syncthreads();
    int excl = v - sum + (wid > 0 ? wsum[wid - 1] : 0);

    int run = excl;
    for (int i = s0; i < s1; ++i) { g_off[i] = run; run += g_cnt[i]; }
}

// ---------------- 4) fill CSR slots ----------------
__global__ void fill_kernel(const int* __restrict__ s0p, const int* __restrict__ d0, int E0,
                            const int* __restrict__ s1p, const int* __restrict__ d1, int E1,
                            const int* __restrict__ s2p, const int* __restrict__ d2, int E2)
{
    int i = blockIdx.x * blockDim.x + threadIdx.x;
    int g, s;
    if (i < E0)                { g = d0[i];                s = s0p[i]; }
    else if (i < E0 + E1)      { g = NU + d1[i - E0];      s = s1p[i - E0]; }
    else if (i < E0 + E1 + E2) { g = 2 * NU + d2[i - E0 - E1]; s = s2p[i - E0 - E1]; }
    else return;
    int pos = g_off[g] + atomicAdd(&g_cur[g], 1);
    g_csr[pos] = s;
}

// ---------------- 5) gather-aggregate: one warp per (etype, node) ----------------
__global__ __launch_bounds__(256) void csr_agg_kernel(
    const float* __restrict__ feat_user, const float* __restrict__ feat_item)
{
    int g    = blockIdx.x * 8 + (threadIdx.x >> 5);
    int lane = threadIdx.x & 31;
    if (g >= 3 * NU) return;

    int et   = g / NU;
    int node = g - et * NU;

    const float* feat = (et == 1) ? feat_item : feat_user;
    float* agg = (et == 0) ? g_agg_ui : (et == 1) ? g_agg_iu : g_agg_uu;
    float* deg = (et == 0) ? g_deg_ui : (et == 1) ? g_deg_iu : g_deg_uu;

    int off = g_off[g];
    int n   = g_cnt[g];

    float4 acc0 = make_float4(0.f, 0.f, 0.f, 0.f);
    float4 acc1 = make_float4(0.f, 0.f, 0.f, 0.f);

    for (int base = 0; base < n; base += 32) {
        int m = (n - base < 32) ? (n - base) : 32;
        int idx = (lane < m) ? g_csr[off + base + lane] : 0;
        int j = 0;
        for (; j + 2 <= m; j += 2) {
            int sA = __shfl_sync(0xffffffffu, idx, j);
            int sB = __shfl_sync(0xffffffffu, idx, j + 1);
            float4 vA = reinterpret_cast<const float4*>(feat + (size_t)sA * D)[lane];
            float4 vB = reinterpret_cast<const float4*>(feat + (size_t)sB * D)[lane];
            acc0.x += vA.x; acc0.y += vA.y; acc0.z += vA.z; acc0.w += vA.w;
            acc1.x += vB.x; acc1.y += vB.y; acc1.z += vB.z; acc1.w += vB.w;
        }
        if (j < m) {
            int sA = __shfl_sync(0xffffffffu, idx, j);
            float4 vA = reinterpret_cast<const float4*>(feat + (size_t)sA * D)[lane];
            acc0.x += vA.x; acc0.y += vA.y; acc0.z += vA.z; acc0.w += vA.w;
        }
    }
    acc0.x += acc1.x; acc0.y += acc1.y; acc0.z += acc1.z; acc0.w += acc1.w;

    reinterpret_cast<float4*>(agg + (size_t)node * D)[lane] = acc0;
    if (lane == 0) deg[node] = (float)n;
}

// ---------------- 6) fused GEMM — R2's EXACT measured kernel ----------------
// out = mask .* ((agg/deg) @ W + b) [+ prev]
// Block tile 64x128, K chunked by 16, 256 threads, scalar 8x4 micro-tile.
__global__ __launch_bounds__(256) void gemm_agg_kernel(
    const float* __restrict__ W,
    const float* __restrict__ bias,
    float* __restrict__ out,
    int M, int accumulate, int which)
{
    const float* A   = (which == 0) ? g_agg_ui : (which == 1) ? g_agg_iu : g_agg_uu;
    const float* deg = (which == 0) ? g_deg_ui : (which == 1) ? g_deg_iu : g_deg_uu;

    __shared__ float W_s[16 * D];     // 8 KB: current K-chunk of W
    __shared__ float A_s[64 * 16];    // 4 KB: current K-chunk of A tile (pre-scaled)
    __shared__ float s_s[64];         // per-row 1/deg (0 if isolated)
    __shared__ float b_s[D];

    const int t  = threadIdx.x;
    const int tx = t & 31;   // 32 col-groups of 4 (covers 128 cols)
    const int ty = t >> 5;   // 8 row-groups of 8

    const int m0 = blockIdx.x * 64;

    if (t < D) b_s[t] = bias[t];
    if (t < 64) {
        int row = m0 + t;
        float dg = (row < M) ? deg[row] : 0.f;
        s_s[t] = (dg > 0.f) ? (1.f / dg) : 0.f;
    }

    float acc[8][4];
#pragma unroll
    for (int r = 0; r < 8; ++r)
#pragma unroll
        for (int c = 0; c < 4; ++c) acc[r][c] = 0.f;

    // A-load mapping: thread t loads row = t>>2, 4 floats at col (t&3)*4 of the chunk
    const int ar = t >> 2;
    const int ac = (t & 3) * 4;
    const int arow = m0 + ar;

#pragma unroll 1
    for (int kc = 0; kc < 8; ++kc) {
        __syncthreads();
        // stage W chunk: 16x128 floats = 512 float4, 2 per thread
        {
            const float4* Wg = reinterpret_cast<const float4*>(W + (size_t)kc * 16 * D);
            reinterpret_cast<float4*>(W_s)[t]       = Wg[t];
            reinterpret_cast<float4*>(W_s)[t + 256] = Wg[t + 256];
        }
        // stage A chunk with 1/deg scaling folded in
        {
            float4 v = make_float4(0.f, 0.f, 0.f, 0.f);
            if (arow < M)
                v = *reinterpret_cast<const float4*>(A + (size_t)arow * D + kc * 16 + ac);
            float sc = s_s[ar];
            v.x *= sc; v.y *= sc; v.z *= sc; v.w *= sc;
            *reinterpret_cast<float4*>(A_s + ar * 16 + ac) = v;
        }
        __syncthreads();

#pragma unroll
        for (int k = 0; k < 16; ++k) {
            float4 w4 = reinterpret_cast<const float4*>(W_s + k * D)[tx];
#pragma unroll
            for (int r = 0; r < 8; ++r) {
                float a = A_s[(ty * 8 + r) * 16 + k];
                acc[r][0] += a * w4.x;
                acc[r][1] += a * w4.y;
                acc[r][2] += a * w4.z;
                acc[r][3] += a * w4.w;
            }
        }
    }

    // epilogue: bias (masked by deg>0), optional accumulate, store
#pragma unroll
    for (int r = 0; r < 8; ++r) {
        int lr  = ty * 8 + r;
        int row = m0 + lr;
        if (row >= M) continue;
        float mask = (s_s[lr] > 0.f) ? 1.f : 0.f;
        float4 o;
        o.x = acc[r][0] + mask * b_s[tx * 4 + 0];
        o.y = acc[r][1] + mask * b_s[tx * 4 + 1];
        o.z = acc[r][2] + mask * b_s[tx * 4 + 2];
        o.w = acc[r][3] + mask * b_s[tx * 4 + 3];
        float4* dst = reinterpret_cast<float4*>(out + (size_t)row * D) + tx;
        if (accumulate) {
            float4 p = *dst;
            o.x += p.x; o.y += p.y; o.z += p.z; o.w += p.w;
        }
        *dst = o;
    }
}

extern "C" void kernel_launch(void* const* d_in, const int* in_sizes, int n_in,
                              void* d_out, int out_size)
{
    const float* feat_user = (const float*)d_in[0];
    const float* feat_item = (const float*)d_in[1];
    const float* W_ui = (const float*)d_in[2];
    const float* b_ui = (const float*)d_in[3];
    const float* W_iu = (const float*)d_in[4];
    const float* b_iu = (const float*)d_in[5];
    const float* W_uu = (const float*)d_in[6];
    const float* b_uu = (const float*)d_in[7];
    const int* src_ui = (const int*)d_in[8];
    const int* dst_ui = (const int*)d_in[9];
    const int* src_iu = (const int*)d_in[10];
    const int* dst_iu = (const int*)d_in[11];
    const int* src_uu = (const int*)d_in[12];
    const int* dst_uu = (const int*)d_in[13];

    const int E_ui = in_sizes[8];
    const int E_iu = in_sizes[10];
    const int E_uu = in_sizes[12];
    const int Etot = E_ui + E_iu + E_uu;

    float* out      = (float*)d_out;
    float* out_user = out;
    float* out_item = out + (size_t)NU * D;

    (void)n_in; (void)out_size;

    // CSR build + gather aggregation (no float atomics, no big zero pass)
    zero_cnt_kernel<<<(3 * NU + 255) / 256, 256>>>();
    hist_kernel<<<(Etot + 255) / 256, 256>>>(dst_ui, E_ui, dst_iu, E_iu, dst_uu, E_uu);
    scan_kernel<<<1, 1024>>>();
    fill_kernel<<<(Etot + 255) / 256, 256>>>(src_ui, dst_ui, E_ui,
                                             src_iu, dst_iu, E_iu,
                                             src_uu, dst_uu, E_uu);
    csr_agg_kernel<<<(3 * NU + 7) / 8, 256>>>(feat_user, feat_item);

    // R2-measured fused projection: 3 launches, scalar FFMA GEMM
    const int GB_I = (NI + 63) / 64;
    const int GB_U = (NU + 63) / 64;
    gemm_agg_kernel<<<GB_I, 256>>>(W_ui, b_ui, out_item, NI, /*acc=*/0, /*which=*/0);
    gemm_agg_kernel<<<GB_U, 256>>>(W_iu, b_iu, out_user, NU, /*acc=*/0, /*which=*/1);
    gemm_agg_kernel<<<GB_U, 256>>>(W_uu, b_uu, out_user, NU, /*acc=*/1, /*which=*/2);
}